// round 16
// baseline (speedup 1.0000x reference)
#include <cuda_runtime.h>
#include <cuda_fp16.h>
#include <cstdint>

#define NN    512
#define SS    64
#define TRS   20
#define STEPS 20
#define NB    (TRS*STEPS)      /* 400 */
#define NBLK  128
#define NWTOT 512              /* total node warps (one per node) */

/* ---- gemm v3 smem layout (4-buffer A pipeline) ---- */
#define APITCH 520                       /* halves per A row (1040B, odd 16B parity) */
#define BPITCH 72                        /* halves per B row (144B, odd 16B parity) */
#define A_BUF_BYTES (16*APITCH*2)        /* 16640 */
#define B_BYTES     (512*BPITCH*2)       /* 73728 */
#define GEMM_SMEM   (B_BYTES + 4*A_BUF_BYTES)  /* 140288 */

// ---------------- device globals (no runtime allocation allowed) ------------
__device__ float  g_lap[NN*NN];            // w scratch, then full laplacian (fp32, incl diag)
__device__ __half g_lap_h[NN*NN];          // w_n (SYMMETRIC, zero diag) fp16 for MMA
__device__ float  g_rowsumraw[NN];
__device__ float  g_sqpart[NN];
__device__ float  g_rowsum[NN];
__device__ float  g_G0[NB*NN*SS];          // w_n @ e0 for all 400 batches: 52.4 MB
__device__ float  g_EmBuf[2*NN];           // ping-pong Em exchange
__device__ __align__(16) unsigned g_count4[4];   // 4 spread arrival counters (one 16B sector)

// ---------------- scoped sync helpers (no CCTL.IVALL!) ----------------------
__device__ __forceinline__ void red_release_gpu(unsigned* p, unsigned v) {
    asm volatile("red.release.gpu.global.add.u32 [%0], %1;"
                 :: "l"(p), "r"(v) : "memory");
}
__device__ __forceinline__ unsigned ld_acquire_sum4(const unsigned* p) {
    unsigned a0, a1, a2, a3;
    asm volatile("ld.acquire.gpu.global.v4.u32 {%0,%1,%2,%3}, [%4];"
                 : "=r"(a0), "=r"(a1), "=r"(a2), "=r"(a3) : "l"(p) : "memory");
    return (a0 + a1) + (a2 + a3);        // u32: max total 512*401 << 2^32
}
__device__ __forceinline__ void cp_async16(unsigned dst, const void* src) {
    asm volatile("cp.async.cg.shared.global [%0], [%1], 16;" :: "r"(dst), "l"(src));
}

// ---------------- prep: w + partial sums -------------------------------------
__global__ void prep_w(const float* __restrict__ sc, const float* __restrict__ gc) {
    int i = blockIdx.x, tid = threadIdx.x;
    float rs = 0.f, ssq = 0.f;
    for (int j = tid; j < NN; j += 256) {
        float wv = 0.5f * (expf(gc[i*NN + j]) * sc[i*NN + j]
                         + expf(gc[j*NN + i]) * sc[j*NN + i]);
        g_lap[i*NN + j] = wv;
        rs += wv; ssq += wv*wv;
    }
    __shared__ float sr[8], sq[8];
    #pragma unroll
    for (int o = 16; o; o >>= 1) {
        rs  += __shfl_down_sync(0xffffffffu, rs, o);
        ssq += __shfl_down_sync(0xffffffffu, ssq, o);
    }
    if ((tid & 31) == 0) { sr[tid>>5] = rs; sq[tid>>5] = ssq; }
    __syncthreads();
    if (tid == 0) {
        float r = 0.f, s2 = 0.f;
        #pragma unroll
        for (int w = 0; w < 8; w++) { r += sr[w]; s2 += sq[w]; }
        g_rowsumraw[i] = r; g_sqpart[i] = s2;
    }
}

// ---------------- fused norm + laplacian --------------------------------------
__global__ void prep_lap(int dummy) {
    int i = blockIdx.x, tid = threadIdx.x;   // 512 blocks x 256 threads
    __shared__ float sm[256];
    float s = g_sqpart[tid] + g_sqpart[tid + 256];
    sm[tid] = s;
    __syncthreads();
    for (int o = 128; o; o >>= 1) { if (tid < o) sm[tid] += sm[tid+o]; __syncthreads(); }
    const float inv  = rsqrtf(sm[0]);
    const float diag = g_rowsumraw[i] * inv;
    for (int j = tid; j < NN; j += 256) {
        float wn = g_lap[i*NN + j] * inv;       // w_n (diag entries are 0)
        g_lap_h[i*NN + j] = __float2half_rn(wn);
        g_lap[i*NN + j]   = (j == i) ? (wn - diag) : wn;  // full laplacian fp32
    }
    if (tid == 0) g_rowsum[i] = diag;
    if (i == 0 && tid < 4) g_count4[tid] = 0u;  // reset barrier for this launch
    (void)dummy;
}

// ---------------- batched GEMM v3: 4-buffer cp.async pipeline, 1 sync/chunk --
__global__ void __launch_bounds__(512) gemm_k(const float* __restrict__ nE0) {
    extern __shared__ __align__(16) char smem_raw[];
    __half* Bs = (__half*)smem_raw;
    const unsigned As_u32 = (unsigned)__cvta_generic_to_shared(smem_raw + B_BYTES);

    const int b = blockIdx.x, tid = threadIdx.x, warp = tid >> 5, lane = tid & 31;
    const float* Bg = nE0 + (size_t)b * (NN*SS);
    float* C = g_G0 + (size_t)b * (NN*SS);

    const int lgrp = lane >> 3, lrow = lane & 7;
    const int m0 = warp * 32;

    // stage B whole: 512 k-rows x 64 samples
    #pragma unroll
    for (int i = 0; i < 16; i++) {
        int e = tid + i*512;
        int k = e >> 4, s4 = e & 15;
        float4 vv = *(const float4*)(Bg + (size_t)k*SS + s4*4);
        __half2* dst = (__half2*)&Bs[k*BPITCH + s4*4];
        dst[0] = __floats2half2_rn(vv.x, vv.y);
        dst[1] = __floats2half2_rn(vv.z, vv.w);
    }

    // prologue: issue A chunks 0,1,2 into buffers 0,1,2
    #pragma unroll
    for (int c = 0; c < 3; c++) {
        #pragma unroll
        for (int i = 0; i < 2; i++) {
            int e = tid + i*512;
            int r = e >> 6, c16 = e & 63;
            cp_async16(As_u32 + (c & 3)*A_BUF_BYTES + r*(APITCH*2) + c16*16,
                       g_lap_h + (size_t)(c*16 + r)*NN + c16*8);
        }
        asm volatile("cp.async.commit_group;" ::: "memory");
    }

    float acc[2][2][4][4];
    #pragma unroll
    for (int mt = 0; mt < 2; mt++)
        #pragma unroll
        for (int h = 0; h < 2; h++)
            #pragma unroll
            for (int nt = 0; nt < 4; nt++)
                #pragma unroll
                for (int c = 0; c < 4; c++) acc[mt][h][nt][c] = 0.f;

    const int b_row = (lgrp & 1)*8 + lrow;
    const int b_col = (lgrp >> 1)*8;
    const int a_row = (lgrp >> 1)*8 + lrow;
    const int a_colq = (lgrp & 1)*8;

    #pragma unroll 1
    for (int ck = 0; ck < 32; ck++) {
        if (ck <= 29)      asm volatile("cp.async.wait_group 2;" ::: "memory");
        else if (ck == 30) asm volatile("cp.async.wait_group 1;" ::: "memory");
        else               asm volatile("cp.async.wait_group 0;" ::: "memory");
        __syncthreads();   // chunk ck visible; everyone done computing ck-1

        if (ck <= 28) {    // issue chunk ck+3 into buffer (ck+3)&3
            const int cn = ck + 3;
            #pragma unroll
            for (int i = 0; i < 2; i++) {
                int e = tid + i*512;
                int r = e >> 6, c16 = e & 63;
                cp_async16(As_u32 + (cn & 3)*A_BUF_BYTES + r*(APITCH*2) + c16*16,
                           g_lap_h + (size_t)(cn*16 + r)*NN + c16*8);
            }
            asm volatile("cp.async.commit_group;" ::: "memory");
        }

        const int k0 = ck * 16;
        const int cur = ck & 3;
        unsigned bq[2][2][4];
        #pragma unroll
        for (int h = 0; h < 2; h++)
            #pragma unroll
            for (int nh = 0; nh < 2; nh++) {
                unsigned addr = (unsigned)__cvta_generic_to_shared(
                    &Bs[(k0 + b_row)*BPITCH + h*32 + nh*16 + b_col]);
                asm volatile(
                    "ldmatrix.sync.aligned.m8n8.x4.trans.shared.b16 {%0,%1,%2,%3},[%4];"
                    : "=r"(bq[h][nh][0]), "=r"(bq[h][nh][1]),
                      "=r"(bq[h][nh][2]), "=r"(bq[h][nh][3])
                    : "r"(addr));
            }

        #pragma unroll
        for (int mt = 0; mt < 2; mt++) {
            unsigned aq[4];
            unsigned aaddr = As_u32 + cur*A_BUF_BYTES
                           + a_row*(APITCH*2) + (m0 + mt*16 + a_colq)*2;
            asm volatile(
                "ldmatrix.sync.aligned.m8n8.x4.trans.shared.b16 {%0,%1,%2,%3},[%4];"
                : "=r"(aq[0]), "=r"(aq[1]), "=r"(aq[2]), "=r"(aq[3])
                : "r"(aaddr));
            #pragma unroll
            for (int h = 0; h < 2; h++) {
                #pragma unroll
                for (int nt = 0; nt < 4; nt++) {
                    unsigned b0 = bq[h][nt >> 1][(nt & 1)*2 + 0];
                    unsigned b1 = bq[h][nt >> 1][(nt & 1)*2 + 1];
                    asm volatile(
                        "mma.sync.aligned.m16n8k16.row.col.f32.f16.f16.f32 "
                        "{%0,%1,%2,%3},{%4,%5,%6,%7},{%8,%9},{%0,%1,%2,%3};\n"
                        : "+f"(acc[mt][h][nt][0]), "+f"(acc[mt][h][nt][1]),
                          "+f"(acc[mt][h][nt][2]), "+f"(acc[mt][h][nt][3])
                        : "r"(aq[0]), "r"(aq[1]), "r"(aq[2]), "r"(aq[3]),
                          "r"(b0), "r"(b1));
                }
            }
        }
    }

    #pragma unroll
    for (int mt = 0; mt < 2; mt++) {
        int r = m0 + mt*16 + (lane >> 2);
        #pragma unroll
        for (int h = 0; h < 2; h++)
            #pragma unroll
            for (int nt = 0; nt < 4; nt++) {
                int c = h*32 + nt*8 + (lane & 3)*2;
                *(float2*)&C[(size_t)r*SS + c]       = make_float2(acc[mt][h][nt][0], acc[mt][h][nt][1]);
                *(float2*)&C[(size_t)(r + 8)*SS + c] = make_float2(acc[mt][h][nt][2], acc[mt][h][nt][3]);
            }
    }
}

// ---------------- fast device math ------------------------------------------
__device__ __forceinline__ float tanh_pos(float x) {  // tanh(relu(x))
    x = fmaxf(x, 0.0f);
    float e = __expf(-2.0f * x);
    return __fdividef(1.0f - e, 1.0f + e);
}
__device__ __forceinline__ float ftanh(float x) {     // fast full-range tanh
    float ax = fabsf(x);
    float e = __expf(-2.0f * ax);
    float r = __fdividef(1.0f - e, 1.0f + e);
    return copysignf(r, x);
}
__device__ __forceinline__ float h_tf(float a, float bb, float d, float z) {
    float x   = fmaf(a, z, -bb);
    float num = 1e-5f + fabsf(x);
    float den = fmaf(1e-5f, d, fabsf(1.0f - __expf(-d * x)));
    return __fdividef(num, den);
}

// ---------------- main sequential loop (EXACT R14 = measured best 883us) ----
// Independent warps; prefetch issued BEFORE the wait (in flight one full
// period — R15 proved moving it after the release costs ~250 cyc/step).
__global__ void __launch_bounds__(128) main_k(
    const float* __restrict__ ext,  const float* __restrict__ hx,
    const float* __restrict__ nE0,  const float* __restrict__ nI0,
    const float* __restrict__ nE,   const float* __restrict__ nI,
    const float* __restrict__ nbold,
    const float* __restrict__ pg,   const float* __restrict__ pgEE,
    const float* __restrict__ pgIE, const float* __restrict__ pgEI,
    const float* __restrict__ pstdin, const float* __restrict__ pstdout,
    float* __restrict__ out)
{
    const int warp = threadIdx.x >> 5, lane = threadIdx.x & 31;
    const int n = blockIdx.x * 4 + warp;      // warp-per-node
    unsigned* const ctr = &g_count4[0];
    unsigned* const my_ctr = &g_count4[warp];

    const float g     = pg[0];
    const float gEE   = 0.001f + fmaxf(pgEE[0], 0.0f);
    const float gIE   = 0.001f + fmaxf(pgIE[0], 0.0f);
    const float gEI   = 0.001f + fmaxf(pgEI[0], 0.0f);
    const float sin_e = 0.02f + fmaxf(pstdin[0], 0.0f);
    const float sout  = fmaxf(pstdout[0], 0.0f);
    const float sq_si = 0.22360680f * sin_e;
    const float g02   = g * 0.02f;
    const float rowsum_n = g_rowsum[n];

    // lap row pinned in registers as float4 quads (never changes)
    float4 rv[4];
    {
        const float4* lr4 = (const float4*)(g_lap + n*NN);
        #pragma unroll
        for (int r = 0; r < 4; r++) rv[r] = lr4[lane + 32*r];
    }

    // node state, redundant in all lanes
    float hxE = hx[n*6 + 0], hxI = hx[n*6 + 1];
    float x = hx[n*6 + 2], f = hx[n*6 + 3], v = hx[n*6 + 4], q = hx[n*6 + 5];

    // publish Em0 and arrive (round 0): stcg + direct release-REDG
    if (lane == 0) {
        __stcg(&g_EmBuf[n], hxE);
        red_release_gpu(my_ctr, 1u);
    }

    // load noise(0), do local precompute for b=0 (samples 2*lane, 2*lane+1)
    const size_t soff = (size_t)n*SS + 2*lane;
    float2 c_e0 = *(const float2*)(nE0 + soff);
    float2 c_i0 = *(const float2*)(nI0 + soff);
    float2 c_eE = *(const float2*)(nE  + soff);
    float2 c_eI = *(const float2*)(nI  + soff);
    float2 c_G0 = *(const float2*)(g_G0 + soff);
    float  c_ex = ext[(n*STEPS + 0)*TRS + 0];

    float2 preIE, preEn, cE2; float ipS;
    {
        float Ex = fmaf(0.02f, c_e0.x, hxE), Ey = fmaf(0.02f, c_e0.y, hxE);
        float Ix = fmaf(0.001f, c_i0.x, hxI), Iy = fmaf(0.001f, c_i0.y, hxI);
        float bias = 0.32f + 0.02f*c_ex;
        preIE.x = bias + gEE*Ex - gIE*Ix + g02*(c_G0.x - rowsum_n*c_e0.x);
        preIE.y = bias + gEE*Ey - gIE*Iy + g02*(c_G0.y - rowsum_n*c_e0.y);
        float IIx = tanh_pos(0.224f + gEI*Ex - Ix);
        float IIy = tanh_pos(0.224f + gEI*Ey - Iy);
        float rIx = h_tf(615.0f, 177.0f, 0.087f, IIx);
        float rIy = h_tf(615.0f, 177.0f, 0.087f, IIy);
        float Ipx = tanh_pos(Ix + 0.05f*(rIx - 100.0f*Ix) + sq_si*c_eI.x);
        float Ipy = tanh_pos(Iy + 0.05f*(rIy - 100.0f*Iy) + sq_si*c_eI.y);
        ipS = Ipx + Ipy;
        #pragma unroll
        for (int o = 16; o; o >>= 1) ipS += __shfl_xor_sync(0xffffffffu, ipS, o);
        preEn.x = 0.5f*Ex + sq_si*c_eE.x;  preEn.y = 0.5f*Ey + sq_si*c_eE.y;
        cE2.x = 0.03205f*(1.0f - Ex);      cE2.y = 0.03205f*(1.0f - Ey);
    }

    unsigned target = NWTOT;
    int st = 0, tr = 0;

    for (int b = 0; b < NB; b++) {
        int st1 = st + 1, tr1 = tr;
        if (st1 == STEPS) { st1 = 0; tr1 = tr + 1; }

        // issue prefetch for b+1 (in flight across wait + critical path)
        float2 p_e0, p_i0, p_eE, p_eI, p_G0; float p_ex = 0.f;
        if (b + 1 < NB) {
            const size_t nb = (size_t)(b + 1)*(NN*SS) + soff;
            p_e0 = __ldcs((const float2*)(nE0 + nb));
            p_i0 = __ldcs((const float2*)(nI0 + nb));
            p_eE = __ldcs((const float2*)(nE  + nb));
            p_eI = __ldcs((const float2*)(nI  + nb));
            p_G0 = __ldcs((const float2*)(g_G0 + nb));
            p_ex = __ldg(ext + (n*STEPS + st1)*TRS + tr1);
        }

        // ---- wait: one 16B acquire load of all 4 counters, sum vs target ----
        while (ld_acquire_sum4(ctr) < target) { }

        // ---- critical path: matvec -> IE -> rE -> Ep -> reduce -> publish ----
        const float4* em4 = (const float4*)(g_EmBuf + (b & 1)*NN);
        float a0, a1, a2, a3;
        {
            float4 e0 = __ldcg(em4 + lane);
            float4 e1 = __ldcg(em4 + lane + 32);
            float4 e2 = __ldcg(em4 + lane + 64);
            float4 e3 = __ldcg(em4 + lane + 96);
            a0 = rv[0].x*e0.x; a1 = rv[0].y*e0.y; a2 = rv[0].z*e0.z; a3 = rv[0].w*e0.w;
            a0 = fmaf(rv[1].x,e1.x,a0); a1 = fmaf(rv[1].y,e1.y,a1);
            a2 = fmaf(rv[1].z,e1.z,a2); a3 = fmaf(rv[1].w,e1.w,a3);
            a0 = fmaf(rv[2].x,e2.x,a0); a1 = fmaf(rv[2].y,e2.y,a1);
            a2 = fmaf(rv[2].z,e2.z,a2); a3 = fmaf(rv[2].w,e2.w,a3);
            a0 = fmaf(rv[3].x,e3.x,a0); a1 = fmaf(rv[3].y,e3.y,a1);
            a2 = fmaf(rv[3].z,e3.z,a2); a3 = fmaf(rv[3].w,e3.w,a3);
        }
        float lv = (a0 + a1) + (a2 + a3);
        #pragma unroll
        for (int o = 16; o; o >>= 1) lv += __shfl_xor_sync(0xffffffffu, lv, o);
        const float glv = g * lv;

        float IEx = tanh_pos(glv + preIE.x);
        float IEy = tanh_pos(glv + preIE.y);
        float rEx = h_tf(310.0f, 125.0f, 0.16f, IEx);
        float rEy = h_tf(310.0f, 125.0f, 0.16f, IEy);
        float eS  = tanh_pos(fmaf(cE2.x, rEx, preEn.x))
                  + tanh_pos(fmaf(cE2.y, rEy, preEn.y));
        #pragma unroll
        for (int o = 16; o; o >>= 1) eS += __shfl_xor_sync(0xffffffffu, eS, o);
        const float Em = fmaxf(eS * (1.0f/64.0f), 1e-5f);
        const float Im = fmaxf(ipS * (1.0f/64.0f), 1e-5f);

        if (lane == 0) {
            __stcg(&g_EmBuf[((b + 1) & 1)*NN + n], Em);
            red_release_gpu(my_ctr, 1u);
        }
        target += NWTOT;

        // ---- off critical path: balloon ODE (all lanes, redundant) ----
        hxE = Em; hxI = Im;
        {
            float v_a = __powf(v, 3.125f);
            float xn = x + 0.05f*(Em - x*(1.0f/0.65f) - (f - 1.0f)*(1.0f/0.41f));
            float fn = f + 0.05f*x;
            float vn = v + (0.05f/0.98f)*(f - v_a);
            float qn = q + (0.05f/0.98f)*(f*(1.0f - __powf(0.66f, __fdividef(1.0f, f)))*(1.0f/0.34f)
                                          - q*__fdividef(v_a, v));
            x = ftanh(xn);
            f = 1.0f + ftanh(fn - 1.0f);
            v = 1.0f + ftanh(vn - 1.0f);
            q = 1.0f + ftanh(qn - 1.0f);
            if (st == STEPS - 1 && lane == 0) {
                out[n*TRS + tr] = sout * nbold[tr*NN + n]
                    + (100.0f*0.02f/0.34f) * (2.38f*(1.0f - q)
                                            + 2.0f*(1.0f - __fdividef(q, v))
                                            + 0.48f*(1.0f - v));
            }
        }
        st = st1; tr = tr1;

        // ---- local precompute for b+1 (consumes prefetched regs) ----
        if (b + 1 < NB) {
            float Ex = fmaf(0.02f, p_e0.x, hxE), Ey = fmaf(0.02f, p_e0.y, hxE);
            float Ix = fmaf(0.001f, p_i0.x, hxI), Iy = fmaf(0.001f, p_i0.y, hxI);
            float bias = 0.32f + 0.02f*p_ex;
            preIE.x = bias + gEE*Ex - gIE*Ix + g02*(p_G0.x - rowsum_n*p_e0.x);
            preIE.y = bias + gEE*Ey - gIE*Iy + g02*(p_G0.y - rowsum_n*p_e0.y);
            float IIx = tanh_pos(0.224f + gEI*Ex - Ix);
            float IIy = tanh_pos(0.224f + gEI*Ey - Iy);
            float rIx = h_tf(615.0f, 177.0f, 0.087f, IIx);
            float rIy = h_tf(615.0f, 177.0f, 0.087f, IIy);
            float Ipx = tanh_pos(Ix + 0.05f*(rIx - 100.0f*Ix) + sq_si*p_eI.x);
            float Ipy = tanh_pos(Iy + 0.05f*(rIy - 100.0f*Iy) + sq_si*p_eI.y);
            ipS = Ipx + Ipy;
            #pragma unroll
            for (int o = 16; o; o >>= 1) ipS += __shfl_xor_sync(0xffffffffu, ipS, o);
            preEn.x = 0.5f*Ex + sq_si*p_eE.x;  preEn.y = 0.5f*Ey + sq_si*p_eE.y;
            cE2.x = 0.03205f*(1.0f - Ex);      cE2.y = 0.03205f*(1.0f - Ey);
        }
    }
}

// ---------------- launch ----------------------------------------------------
extern "C" void kernel_launch(void* const* d_in, const int* in_sizes, int n_in,
                              void* d_out, int out_size) {
    (void)in_sizes; (void)n_in; (void)out_size;
    const float* external = (const float*)d_in[0];
    const float* hx       = (const float*)d_in[1];
    /* d_in[2] = hE : unused by the reference */
    const float* sc       = (const float*)d_in[3];
    const float* gc       = (const float*)d_in[4];
    const float* pg       = (const float*)d_in[5];
    const float* pgEE     = (const float*)d_in[6];
    const float* pgIE     = (const float*)d_in[7];
    const float* pgEI     = (const float*)d_in[8];
    const float* pstdin   = (const float*)d_in[9];
    const float* pstdout  = (const float*)d_in[10];
    const float* nE0      = (const float*)d_in[11];
    const float* nI0      = (const float*)d_in[12];
    const float* nEn      = (const float*)d_in[13];
    const float* nIn      = (const float*)d_in[14];
    const float* nbold    = (const float*)d_in[15];
    float* out = (float*)d_out;

    cudaFuncSetAttribute(gemm_k, cudaFuncAttributeMaxDynamicSharedMemorySize, GEMM_SMEM);

    prep_w   <<<NN, 256>>>(sc, gc);
    prep_lap <<<NN, 256>>>(0);
    gemm_k   <<<NB, 512, GEMM_SMEM>>>(nE0);
    main_k   <<<NBLK, 128>>>(external, hx, nE0, nI0, nEn, nIn, nbold,
                             pg, pgEE, pgIE, pgEI, pstdin, pstdout, out);
}

// round 17
// speedup vs baseline: 1.1341x; 1.1341x over previous
#include <cuda_runtime.h>
#include <cuda_fp16.h>
#include <cstdint>

#define NN    512
#define SS    64
#define TRS   20
#define STEPS 20
#define NB    (TRS*STEPS)      /* 400 */
#define NBLK  128
#define NWTOT 512              /* total node warps (one per node) */

/* ---- gemm v2 smem layout ---- */
#define APITCH 520                       /* halves per A row (1040B, odd 16B parity) */
#define BPITCH 72                        /* halves per B row (144B, odd 16B parity) */
#define A_BUF_BYTES (16*APITCH*2)        /* 16640 */
#define B_BYTES     (512*BPITCH*2)       /* 73728 */
#define GEMM_SMEM   (B_BYTES + 2*A_BUF_BYTES)  /* 107008 */

// ---------------- device globals (no runtime allocation allowed) ------------
__device__ float  g_lap[NN*NN];            // w scratch, then full laplacian (fp32, incl diag)
__device__ __half g_lap_h[NN*NN];          // w_n (SYMMETRIC, zero diag) fp16 for MMA
__device__ float  g_rowsumraw[NN];
__device__ float  g_sqpart[NN];
__device__ float  g_rowsum[NN];
__device__ float  g_G0[NB*NN*SS];          // w_n @ e0 for all 400 batches: 52.4 MB
__device__ float  g_EmBuf[2*NN];           // ping-pong Em exchange
__device__ __align__(16) unsigned g_count4[4];   // 4 spread arrival counters (one 16B sector)

// ---------------- scoped sync helpers (no CCTL.IVALL!) ----------------------
__device__ __forceinline__ void red_release_gpu(unsigned* p, unsigned v) {
    asm volatile("red.release.gpu.global.add.u32 [%0], %1;"
                 :: "l"(p), "r"(v) : "memory");
}
__device__ __forceinline__ unsigned long long ld_acquire_sum4(const unsigned* p) {
    unsigned a0, a1, a2, a3;
    asm volatile("ld.acquire.gpu.global.v4.u32 {%0,%1,%2,%3}, [%4];"
                 : "=r"(a0), "=r"(a1), "=r"(a2), "=r"(a3) : "l"(p) : "memory");
    return (unsigned long long)a0 + a1 + a2 + a3;
}
__device__ __forceinline__ void cp_async16(unsigned dst, const void* src) {
    asm volatile("cp.async.cg.shared.global [%0], [%1], 16;" :: "r"(dst), "l"(src));
}

// ---------------- prep: w + partial sums -------------------------------------
__global__ void prep_w(const float* __restrict__ sc, const float* __restrict__ gc) {
    int i = blockIdx.x, tid = threadIdx.x;
    float rs = 0.f, ssq = 0.f;
    for (int j = tid; j < NN; j += 256) {
        float wv = 0.5f * (expf(gc[i*NN + j]) * sc[i*NN + j]
                         + expf(gc[j*NN + i]) * sc[j*NN + i]);
        g_lap[i*NN + j] = wv;
        rs += wv; ssq += wv*wv;
    }
    __shared__ float sr[8], sq[8];
    #pragma unroll
    for (int o = 16; o; o >>= 1) {
        rs  += __shfl_down_sync(0xffffffffu, rs, o);
        ssq += __shfl_down_sync(0xffffffffu, ssq, o);
    }
    if ((tid & 31) == 0) { sr[tid>>5] = rs; sq[tid>>5] = ssq; }
    __syncthreads();
    if (tid == 0) {
        float r = 0.f, s2 = 0.f;
        #pragma unroll
        for (int w = 0; w < 8; w++) { r += sr[w]; s2 += sq[w]; }
        g_rowsumraw[i] = r; g_sqpart[i] = s2;
    }
}

// ---------------- fused norm + laplacian --------------------------------------
__global__ void prep_lap(int dummy) {
    int i = blockIdx.x, tid = threadIdx.x;   // 512 blocks x 256 threads
    __shared__ float sm[256];
    float s = g_sqpart[tid] + g_sqpart[tid + 256];
    sm[tid] = s;
    __syncthreads();
    for (int o = 128; o; o >>= 1) { if (tid < o) sm[tid] += sm[tid+o]; __syncthreads(); }
    const float inv  = rsqrtf(sm[0]);
    const float diag = g_rowsumraw[i] * inv;
    for (int j = tid; j < NN; j += 256) {
        float wn = g_lap[i*NN + j] * inv;       // w_n (diag entries are 0)
        g_lap_h[i*NN + j] = __float2half_rn(wn);
        g_lap[i*NN + j]   = (j == i) ? (wn - diag) : wn;  // full laplacian fp32
    }
    if (tid == 0) g_rowsum[i] = diag;
    if (i == 0 && tid < 4) g_count4[tid] = 0u;  // reset barrier for this launch
    (void)dummy;
}

// ---------------- batched GEMM v2: double-buffered cp.async A, smem B --------
__global__ void __launch_bounds__(512) gemm_k(const float* __restrict__ nE0) {
    extern __shared__ __align__(16) char smem_raw[];
    __half* Bs = (__half*)smem_raw;
    const unsigned As_u32 = (unsigned)__cvta_generic_to_shared(smem_raw + B_BYTES);

    const int b = blockIdx.x, tid = threadIdx.x, warp = tid >> 5, lane = tid & 31;
    const float* Bg = nE0 + (size_t)b * (NN*SS);
    float* C = g_G0 + (size_t)b * (NN*SS);

    const int lgrp = lane >> 3, lrow = lane & 7;
    const int m0 = warp * 32;

    #pragma unroll
    for (int i = 0; i < 16; i++) {
        int e = tid + i*512;
        int k = e >> 4, s4 = e & 15;
        float4 vv = *(const float4*)(Bg + (size_t)k*SS + s4*4);
        __half2* dst = (__half2*)&Bs[k*BPITCH + s4*4];
        dst[0] = __floats2half2_rn(vv.x, vv.y);
        dst[1] = __floats2half2_rn(vv.z, vv.w);
    }

    #pragma unroll
    for (int i = 0; i < 2; i++) {
        int e = tid + i*512;
        int r = e >> 6, c16 = e & 63;
        cp_async16(As_u32 + r*(APITCH*2) + c16*16,
                   g_lap_h + (size_t)r*NN + c16*8);
    }
    asm volatile("cp.async.commit_group;" ::: "memory");

    float acc[2][2][4][4];
    #pragma unroll
    for (int mt = 0; mt < 2; mt++)
        #pragma unroll
        for (int h = 0; h < 2; h++)
            #pragma unroll
            for (int nt = 0; nt < 4; nt++)
                #pragma unroll
                for (int c = 0; c < 4; c++) acc[mt][h][nt][c] = 0.f;

    const int b_row = (lgrp & 1)*8 + lrow;
    const int b_col = (lgrp >> 1)*8;
    const int a_row = (lgrp >> 1)*8 + lrow;
    const int a_colq = (lgrp & 1)*8;

    #pragma unroll 1
    for (int ck = 0; ck < 32; ck++) {
        const int cur = ck & 1;
        __syncthreads();
        if (ck < 31) {
            const int k0n = (ck + 1)*16;
            #pragma unroll
            for (int i = 0; i < 2; i++) {
                int e = tid + i*512;
                int r = e >> 6, c16 = e & 63;
                cp_async16(As_u32 + (cur^1)*A_BUF_BYTES + r*(APITCH*2) + c16*16,
                           g_lap_h + (size_t)(k0n + r)*NN + c16*8);
            }
            asm volatile("cp.async.commit_group;" ::: "memory");
            asm volatile("cp.async.wait_group 1;" ::: "memory");
        } else {
            asm volatile("cp.async.wait_group 0;" ::: "memory");
        }
        __syncthreads();

        const int k0 = ck * 16;
        unsigned bq[2][2][4];
        #pragma unroll
        for (int h = 0; h < 2; h++)
            #pragma unroll
            for (int nh = 0; nh < 2; nh++) {
                unsigned addr = (unsigned)__cvta_generic_to_shared(
                    &Bs[(k0 + b_row)*BPITCH + h*32 + nh*16 + b_col]);
                asm volatile(
                    "ldmatrix.sync.aligned.m8n8.x4.trans.shared.b16 {%0,%1,%2,%3},[%4];"
                    : "=r"(bq[h][nh][0]), "=r"(bq[h][nh][1]),
                      "=r"(bq[h][nh][2]), "=r"(bq[h][nh][3])
                    : "r"(addr));
            }

        #pragma unroll
        for (int mt = 0; mt < 2; mt++) {
            unsigned aq[4];
            unsigned aaddr = As_u32 + cur*A_BUF_BYTES
                           + a_row*(APITCH*2) + (m0 + mt*16 + a_colq)*2;
            asm volatile(
                "ldmatrix.sync.aligned.m8n8.x4.trans.shared.b16 {%0,%1,%2,%3},[%4];"
                : "=r"(aq[0]), "=r"(aq[1]), "=r"(aq[2]), "=r"(aq[3])
                : "r"(aaddr));
            #pragma unroll
            for (int h = 0; h < 2; h++) {
                #pragma unroll
                for (int nt = 0; nt < 4; nt++) {
                    unsigned b0 = bq[h][nt >> 1][(nt & 1)*2 + 0];
                    unsigned b1 = bq[h][nt >> 1][(nt & 1)*2 + 1];
                    asm volatile(
                        "mma.sync.aligned.m16n8k16.row.col.f32.f16.f16.f32 "
                        "{%0,%1,%2,%3},{%4,%5,%6,%7},{%8,%9},{%0,%1,%2,%3};\n"
                        : "+f"(acc[mt][h][nt][0]), "+f"(acc[mt][h][nt][1]),
                          "+f"(acc[mt][h][nt][2]), "+f"(acc[mt][h][nt][3])
                        : "r"(aq[0]), "r"(aq[1]), "r"(aq[2]), "r"(aq[3]),
                          "r"(b0), "r"(b1));
                }
            }
        }
    }

    #pragma unroll
    for (int mt = 0; mt < 2; mt++) {
        int r = m0 + mt*16 + (lane >> 2);
        #pragma unroll
        for (int h = 0; h < 2; h++)
            #pragma unroll
            for (int nt = 0; nt < 4; nt++) {
                int c = h*32 + nt*8 + (lane & 3)*2;
                *(float2*)&C[(size_t)r*SS + c]       = make_float2(acc[mt][h][nt][0], acc[mt][h][nt][1]);
                *(float2*)&C[(size_t)(r + 8)*SS + c] = make_float2(acc[mt][h][nt][2], acc[mt][h][nt][3]);
            }
    }
}

// ---------------- fast device math ------------------------------------------
__device__ __forceinline__ float tanh_pos(float x) {  // tanh(relu(x))
    x = fmaxf(x, 0.0f);
    float e = __expf(-2.0f * x);
    return __fdividef(1.0f - e, 1.0f + e);
}
__device__ __forceinline__ float ftanh(float x) {     // fast full-range tanh
    float ax = fabsf(x);
    float e = __expf(-2.0f * ax);
    float r = __fdividef(1.0f - e, 1.0f + e);
    return copysignf(r, x);
}
__device__ __forceinline__ float h_tf(float a, float bb, float d, float z) {
    float x   = fmaf(a, z, -bb);
    float num = 1e-5f + fabsf(x);
    float den = fmaf(1e-5f, d, fabsf(1.0f - __expf(-d * x)));
    return __fdividef(num, den);
}

// ---------------- main sequential loop (EXACT R14 = measured best 883us) ----
__global__ void __launch_bounds__(128) main_k(
    const float* __restrict__ ext,  const float* __restrict__ hx,
    const float* __restrict__ nE0,  const float* __restrict__ nI0,
    const float* __restrict__ nE,   const float* __restrict__ nI,
    const float* __restrict__ nbold,
    const float* __restrict__ pg,   const float* __restrict__ pgEE,
    const float* __restrict__ pgIE, const float* __restrict__ pgEI,
    const float* __restrict__ pstdin, const float* __restrict__ pstdout,
    float* __restrict__ out)
{
    const int warp = threadIdx.x >> 5, lane = threadIdx.x & 31;
    const int n = blockIdx.x * 4 + warp;      // warp-per-node
    unsigned* const ctr = &g_count4[0];
    unsigned* const my_ctr = &g_count4[warp];

    const float g     = pg[0];
    const float gEE   = 0.001f + fmaxf(pgEE[0], 0.0f);
    const float gIE   = 0.001f + fmaxf(pgIE[0], 0.0f);
    const float gEI   = 0.001f + fmaxf(pgEI[0], 0.0f);
    const float sin_e = 0.02f + fmaxf(pstdin[0], 0.0f);
    const float sout  = fmaxf(pstdout[0], 0.0f);
    const float sq_si = 0.22360680f * sin_e;
    const float g02   = g * 0.02f;
    const float rowsum_n = g_rowsum[n];

    // lap row pinned in registers as float4 quads (never changes)
    float4 rv[4];
    {
        const float4* lr4 = (const float4*)(g_lap + n*NN);
        #pragma unroll
        for (int r = 0; r < 4; r++) rv[r] = lr4[lane + 32*r];
    }

    // node state, redundant in all lanes
    float hxE = hx[n*6 + 0], hxI = hx[n*6 + 1];
    float x = hx[n*6 + 2], f = hx[n*6 + 3], v = hx[n*6 + 4], q = hx[n*6 + 5];

    // publish Em0 and arrive (round 0): stcg + direct release-REDG
    if (lane == 0) {
        __stcg(&g_EmBuf[n], hxE);
        red_release_gpu(my_ctr, 1u);
    }

    // load noise(0), do local precompute for b=0 (samples 2*lane, 2*lane+1)
    const size_t soff = (size_t)n*SS + 2*lane;
    float2 c_e0 = *(const float2*)(nE0 + soff);
    float2 c_i0 = *(const float2*)(nI0 + soff);
    float2 c_eE = *(const float2*)(nE  + soff);
    float2 c_eI = *(const float2*)(nI  + soff);
    float2 c_G0 = *(const float2*)(g_G0 + soff);
    float  c_ex = ext[(n*STEPS + 0)*TRS + 0];

    float2 preIE, preEn, cE2; float ipS;
    {
        float Ex = fmaf(0.02f, c_e0.x, hxE), Ey = fmaf(0.02f, c_e0.y, hxE);
        float Ix = fmaf(0.001f, c_i0.x, hxI), Iy = fmaf(0.001f, c_i0.y, hxI);
        float bias = 0.32f + 0.02f*c_ex;
        preIE.x = bias + gEE*Ex - gIE*Ix + g02*(c_G0.x - rowsum_n*c_e0.x);
        preIE.y = bias + gEE*Ey - gIE*Iy + g02*(c_G0.y - rowsum_n*c_e0.y);
        float IIx = tanh_pos(0.224f + gEI*Ex - Ix);
        float IIy = tanh_pos(0.224f + gEI*Ey - Iy);
        float rIx = h_tf(615.0f, 177.0f, 0.087f, IIx);
        float rIy = h_tf(615.0f, 177.0f, 0.087f, IIy);
        float Ipx = tanh_pos(Ix + 0.05f*(rIx - 100.0f*Ix) + sq_si*c_eI.x);
        float Ipy = tanh_pos(Iy + 0.05f*(rIy - 100.0f*Iy) + sq_si*c_eI.y);
        ipS = Ipx + Ipy;
        #pragma unroll
        for (int o = 16; o; o >>= 1) ipS += __shfl_xor_sync(0xffffffffu, ipS, o);
        preEn.x = 0.5f*Ex + sq_si*c_eE.x;  preEn.y = 0.5f*Ey + sq_si*c_eE.y;
        cE2.x = 0.03205f*(1.0f - Ex);      cE2.y = 0.03205f*(1.0f - Ey);
    }

    unsigned long long target = NWTOT;
    int st = 0, tr = 0;

    for (int b = 0; b < NB; b++) {
        int st1 = st + 1, tr1 = tr;
        if (st1 == STEPS) { st1 = 0; tr1 = tr + 1; }

        // issue prefetch for b+1 (in flight across wait + critical path)
        float2 p_e0, p_i0, p_eE, p_eI, p_G0; float p_ex = 0.f;
        if (b + 1 < NB) {
            const size_t nb = (size_t)(b + 1)*(NN*SS) + soff;
            p_e0 = __ldcs((const float2*)(nE0 + nb));
            p_i0 = __ldcs((const float2*)(nI0 + nb));
            p_eE = __ldcs((const float2*)(nE  + nb));
            p_eI = __ldcs((const float2*)(nI  + nb));
            p_G0 = __ldcs((const float2*)(g_G0 + nb));
            p_ex = __ldg(ext + (n*STEPS + st1)*TRS + tr1);
        }

        // ---- wait: one 16B acquire load of all 4 counters, sum vs target ----
        while (ld_acquire_sum4(ctr) < target) { }

        // ---- critical path: matvec -> IE -> rE -> Ep -> reduce -> publish ----
        const float4* em4 = (const float4*)(g_EmBuf + (b & 1)*NN);
        float a0, a1, a2, a3;
        {
            float4 e0 = __ldcg(em4 + lane);
            float4 e1 = __ldcg(em4 + lane + 32);
            float4 e2 = __ldcg(em4 + lane + 64);
            float4 e3 = __ldcg(em4 + lane + 96);
            a0 = rv[0].x*e0.x; a1 = rv[0].y*e0.y; a2 = rv[0].z*e0.z; a3 = rv[0].w*e0.w;
            a0 = fmaf(rv[1].x,e1.x,a0); a1 = fmaf(rv[1].y,e1.y,a1);
            a2 = fmaf(rv[1].z,e1.z,a2); a3 = fmaf(rv[1].w,e1.w,a3);
            a0 = fmaf(rv[2].x,e2.x,a0); a1 = fmaf(rv[2].y,e2.y,a1);
            a2 = fmaf(rv[2].z,e2.z,a2); a3 = fmaf(rv[2].w,e2.w,a3);
            a0 = fmaf(rv[3].x,e3.x,a0); a1 = fmaf(rv[3].y,e3.y,a1);
            a2 = fmaf(rv[3].z,e3.z,a2); a3 = fmaf(rv[3].w,e3.w,a3);
        }
        float lv = (a0 + a1) + (a2 + a3);
        #pragma unroll
        for (int o = 16; o; o >>= 1) lv += __shfl_xor_sync(0xffffffffu, lv, o);
        const float glv = g * lv;

        float IEx = tanh_pos(glv + preIE.x);
        float IEy = tanh_pos(glv + preIE.y);
        float rEx = h_tf(310.0f, 125.0f, 0.16f, IEx);
        float rEy = h_tf(310.0f, 125.0f, 0.16f, IEy);
        float eS  = tanh_pos(fmaf(cE2.x, rEx, preEn.x))
                  + tanh_pos(fmaf(cE2.y, rEy, preEn.y));
        #pragma unroll
        for (int o = 16; o; o >>= 1) eS += __shfl_xor_sync(0xffffffffu, eS, o);
        const float Em = fmaxf(eS * (1.0f/64.0f), 1e-5f);
        const float Im = fmaxf(ipS * (1.0f/64.0f), 1e-5f);

        if (lane == 0) {
            __stcg(&g_EmBuf[((b + 1) & 1)*NN + n], Em);
            red_release_gpu(my_ctr, 1u);
        }
        target += NWTOT;

        // ---- off critical path: balloon ODE (all lanes, redundant) ----
        hxE = Em; hxI = Im;
        {
            float v_a = __powf(v, 3.125f);
            float xn = x + 0.05f*(Em - x*(1.0f/0.65f) - (f - 1.0f)*(1.0f/0.41f));
            float fn = f + 0.05f*x;
            float vn = v + (0.05f/0.98f)*(f - v_a);
            float qn = q + (0.05f/0.98f)*(f*(1.0f - __powf(0.66f, __fdividef(1.0f, f)))*(1.0f/0.34f)
                                          - q*__fdividef(v_a, v));
            x = ftanh(xn);
            f = 1.0f + ftanh(fn - 1.0f);
            v = 1.0f + ftanh(vn - 1.0f);
            q = 1.0f + ftanh(qn - 1.0f);
            if (st == STEPS - 1 && lane == 0) {
                out[n*TRS + tr] = sout * nbold[tr*NN + n]
                    + (100.0f*0.02f/0.34f) * (2.38f*(1.0f - q)
                                            + 2.0f*(1.0f - __fdividef(q, v))
                                            + 0.48f*(1.0f - v));
            }
        }
        st = st1; tr = tr1;

        // ---- local precompute for b+1 (consumes prefetched regs) ----
        if (b + 1 < NB) {
            float Ex = fmaf(0.02f, p_e0.x, hxE), Ey = fmaf(0.02f, p_e0.y, hxE);
            float Ix = fmaf(0.001f, p_i0.x, hxI), Iy = fmaf(0.001f, p_i0.y, hxI);
            float bias = 0.32f + 0.02f*p_ex;
            preIE.x = bias + gEE*Ex - gIE*Ix + g02*(p_G0.x - rowsum_n*p_e0.x);
            preIE.y = bias + gEE*Ey - gIE*Iy + g02*(p_G0.y - rowsum_n*p_e0.y);
            float IIx = tanh_pos(0.224f + gEI*Ex - Ix);
            float IIy = tanh_pos(0.224f + gEI*Ey - Iy);
            float rIx = h_tf(615.0f, 177.0f, 0.087f, IIx);
            float rIy = h_tf(615.0f, 177.0f, 0.087f, IIy);
            float Ipx = tanh_pos(Ix + 0.05f*(rIx - 100.0f*Ix) + sq_si*p_eI.x);
            float Ipy = tanh_pos(Iy + 0.05f*(rIy - 100.0f*Iy) + sq_si*p_eI.y);
            ipS = Ipx + Ipy;
            #pragma unroll
            for (int o = 16; o; o >>= 1) ipS += __shfl_xor_sync(0xffffffffu, ipS, o);
            preEn.x = 0.5f*Ex + sq_si*p_eE.x;  preEn.y = 0.5f*Ey + sq_si*p_eE.y;
            cE2.x = 0.03205f*(1.0f - Ex);      cE2.y = 0.03205f*(1.0f - Ey);
        }
    }
}

// ---------------- launch ----------------------------------------------------
extern "C" void kernel_launch(void* const* d_in, const int* in_sizes, int n_in,
                              void* d_out, int out_size) {
    (void)in_sizes; (void)n_in; (void)out_size;
    const float* external = (const float*)d_in[0];
    const float* hx       = (const float*)d_in[1];
    /* d_in[2] = hE : unused by the reference */
    const float* sc       = (const float*)d_in[3];
    const float* gc       = (const float*)d_in[4];
    const float* pg       = (const float*)d_in[5];
    const float* pgEE     = (const float*)d_in[6];
    const float* pgIE     = (const float*)d_in[7];
    const float* pgEI     = (const float*)d_in[8];
    const float* pstdin   = (const float*)d_in[9];
    const float* pstdout  = (const float*)d_in[10];
    const float* nE0      = (const float*)d_in[11];
    const float* nI0      = (const float*)d_in[12];
    const float* nEn      = (const float*)d_in[13];
    const float* nIn      = (const float*)d_in[14];
    const float* nbold    = (const float*)d_in[15];
    float* out = (float*)d_out;

    cudaFuncSetAttribute(gemm_k, cudaFuncAttributeMaxDynamicSharedMemorySize, GEMM_SMEM);

    prep_w   <<<NN, 256>>>(sc, gc);
    prep_lap <<<NN, 256>>>(0);
    gemm_k   <<<NB, 512, GEMM_SMEM>>>(nE0);
    main_k   <<<NBLK, 128>>>(external, hx, nE0, nI0, nEn, nIn, nbold,
                             pg, pgEE, pgIE, pgEI, pstdin, pstdout, out);
}